// round 13
// baseline (speedup 1.0000x reference)
#include <cuda_runtime.h>
#include <math.h>

// Problem shape (fixed by the reference)
#define B_    32
#define C_    512
#define MID_  32
#define HW_   3136          // 56*56
#define HW4_  784           // HW_/4
#define ROWS_ (B_ * C_)     // 16384

// Persistent-kernel geometry: 592 = 148*4 CTAs, guaranteed co-resident at
// 4 CTAs/SM (launch_bounds caps regs at 64: 256*64*4 = 65536 = full RF).
// GB300 has 152 SMs, so residency holds with margin.
#define GRID_ 592
#define NTHR_ 256

// Scratch + sync words (allocation-free rule: __device__ globals)
__device__ float        g_s[ROWS_];    // row means
__device__ float        g_g[ROWS_];    // gates (indexed by row = b*C+c)
__device__ unsigned int g_cnt[B_];     // pooled-row count per batch
__device__ unsigned int g_flag[B_];    // gates-ready flag per batch

// ---------------------------------------------------------------------------
// Init: zero the sync words every replay (graph-deterministic).
// ---------------------------------------------------------------------------
__global__ void se_init() {
    if (threadIdx.x < B_) { g_cnt[threadIdx.x] = 0u; g_flag[threadIdx.x] = 0u; }
}

// ---------------------------------------------------------------------------
// Fused persistent SE kernel.
// Per CTA: pool its strided rows (non-blocking); last-arriver per batch
// computes that batch's gates; scale rows opportunistically as their batch's
// gates become ready (so x rows are re-read while still L2-resident);
// drain any remainder with a spin-wait (deadlock-free: all pooling
// completes unconditionally before any CTA blocks).
// ---------------------------------------------------------------------------
__global__ void __launch_bounds__(NTHR_, 4)
se_fused(const float* __restrict__ x,  const float* __restrict__ w1,
         const float* __restrict__ b1, const float* __restrict__ w2,
         const float* __restrict__ b2, float* __restrict__ out) {
    const int cta  = blockIdx.x;
    const int tid  = threadIdx.x;
    const int warp = tid >> 5;
    const int lane = tid & 31;

    __shared__ float red_sm[8];
    __shared__ float h_sm[MID_];
    __shared__ int   bc_sm;                       // tid0 -> all broadcast

    const int n_my = (ROWS_ - 1 - cta) / GRID_ + 1;   // 27 or 28 rows
    int sdone = 0;

    for (int p = 0; p < n_my; ++p) {
        const int row = cta + p * GRID_;
        const int b   = row >> 9;                 // row / C_

        // ---------------- pool row ----------------
        {
            const float4* __restrict__ xr =
                reinterpret_cast<const float4*>(x + (size_t)row * HW_);
            float acc = 0.0f;
            #pragma unroll 4
            for (int i = tid; i < HW4_; i += NTHR_) {
                float4 v = xr[i];
                acc += (v.x + v.y) + (v.z + v.w);
            }
            #pragma unroll
            for (int o = 16; o > 0; o >>= 1)
                acc += __shfl_xor_sync(0xFFFFFFFFu, acc, o);
            if (lane == 0) red_sm[warp] = acc;
            __syncthreads();
            if (tid == 0) {
                float v = 0.0f;
                #pragma unroll
                for (int w = 0; w < 8; ++w) v += red_sm[w];
                g_s[row] = v * (1.0f / (float)HW_);
                __threadfence();                       // publish s before count
                unsigned old = atomicAdd(&g_cnt[b], 1u);
                bc_sm = (old == (unsigned)(C_ - 1)) ? 1 : 0;
            }
            __syncthreads();
        }

        // -------- last-arriver computes gates for batch b --------
        if (bc_sm) {
            __threadfence();                           // acquire all s[b,*]
            const float* __restrict__ srow = g_s + b * C_;
            #pragma unroll
            for (int j = 0; j < 4; ++j) {
                const int m = warp * 4 + j;
                const float* __restrict__ wrow = w1 + m * C_;
                float a = 0.0f;
                #pragma unroll
                for (int k = 0; k < C_ / 32; ++k)
                    a = fmaf(srow[lane + 32 * k], wrow[lane + 32 * k], a);
                #pragma unroll
                for (int o = 16; o > 0; o >>= 1)
                    a += __shfl_xor_sync(0xFFFFFFFFu, a, o);
                if (lane == 0) h_sm[m] = fmaxf(a + b1[m], 0.0f);
            }
            __syncthreads();
            for (int c = tid; c < C_; c += NTHR_) {
                const float4* __restrict__ w2r =
                    reinterpret_cast<const float4*>(w2 + c * MID_);
                float a = b2[c];
                #pragma unroll
                for (int i = 0; i < MID_ / 4; ++i) {
                    float4 w = w2r[i];
                    a = fmaf(w.x, h_sm[4 * i + 0], a);
                    a = fmaf(w.y, h_sm[4 * i + 1], a);
                    a = fmaf(w.z, h_sm[4 * i + 2], a);
                    a = fmaf(w.w, h_sm[4 * i + 3], a);
                }
                g_g[b * C_ + c] = 1.0f / (1.0f + __expf(-a));
            }
            __threadfence();                           // publish gates
            __syncthreads();
            if (tid == 0) atomicExch(&g_flag[b], 1u);
        }

        // -------- opportunistic scale of ready rows (non-blocking) --------
        while (sdone < p) {
            const int srow = cta + sdone * GRID_;
            const int sb   = srow >> 9;
            if (tid == 0)
                bc_sm = (*(volatile unsigned int*)&g_flag[sb]) != 0u;
            __syncthreads();
            if (!bc_sm) break;
            __threadfence();                           // acquire gates
            const float gv = g_g[srow];
            const float4* __restrict__ xr =
                reinterpret_cast<const float4*>(x + (size_t)srow * HW_);
            float4* __restrict__ orow =
                reinterpret_cast<float4*>(out + (size_t)srow * HW_);
            #pragma unroll 4
            for (int i = tid; i < HW4_; i += NTHR_) {
                float4 v = xr[i];                      // L2-hot (pooled recently)
                v.x *= gv; v.y *= gv; v.z *= gv; v.w *= gv;
                __stcs(&orow[i], v);                   // evict-first stores
            }
            ++sdone;
            __syncthreads();                           // bc_sm reuse safety
        }
    }

    // -------- drain remaining rows (safe to block now) --------
    while (sdone < n_my) {
        const int srow = cta + sdone * GRID_;
        const int sb   = srow >> 9;
        if (tid == 0) {
            while ((*(volatile unsigned int*)&g_flag[sb]) == 0u) __nanosleep(64);
        }
        __syncthreads();
        __threadfence();
        const float gv = g_g[srow];
        const float4* __restrict__ xr =
            reinterpret_cast<const float4*>(x + (size_t)srow * HW_);
        float4* __restrict__ orow =
            reinterpret_cast<float4*>(out + (size_t)srow * HW_);
        #pragma unroll 4
        for (int i = tid; i < HW4_; i += NTHR_) {
            float4 v = xr[i];
            v.x *= gv; v.y *= gv; v.z *= gv; v.w *= gv;
            __stcs(&orow[i], v);
        }
        ++sdone;
        __syncthreads();
    }
}

// ---------------------------------------------------------------------------
// Launch. Inputs (metadata order): x, w1, b1, w2, b2. Output: float32.
// ---------------------------------------------------------------------------
extern "C" void kernel_launch(void* const* d_in, const int* in_sizes, int n_in,
                              void* d_out, int out_size) {
    const float* x  = (const float*)d_in[0];
    const float* w1 = (const float*)d_in[1];
    const float* b1 = (const float*)d_in[2];
    const float* w2 = (const float*)d_in[3];
    const float* b2 = (const float*)d_in[4];
    float* out = (float*)d_out;

    se_init<<<1, 32>>>();
    se_fused<<<GRID_, NTHR_>>>(x, w1, b1, w2, b2, out);
}